// round 1
// baseline (speedup 1.0000x reference)
#include <cuda_runtime.h>

#define T_  1024
#define H_  2048
#define I_  1408
#define E_  16
#define C_  512
#define TK_ 2048   // T_ * 2

// ---------------- scratch (device globals; no allocation allowed) ----------
__device__ int   g_topi[TK_];
__device__ float g_topw[TK_];
__device__ int   g_slot_tok[E_ * C_];   // slot -> source token
__device__ int   g_slot_of_j[TK_];      // flattened (t,k) -> slot, or -1 if dropped
__device__ int   g_cnt[E_];             // valid rows per expert (<= C)
__device__ float g_act[(size_t)E_ * C_ * I_];    // silu(gate)*up, 46 MB
__device__ float g_ybuf[(size_t)E_ * C_ * H_];   // expert output rows, 67 MB

// ---------------- routing: top-2 + deterministic stable capacity assignment
__global__ void router_kernel(const float* __restrict__ logits) {
    int tid = threadIdx.x;
    // phase 1: per-token top-2 (softmax + renormalize == pairwise sigmoid)
    for (int t = tid; t < T_; t += 512) {
        const float* l = logits + t * E_;
        float v[E_];
#pragma unroll
        for (int e = 0; e < E_; e++) v[e] = l[e];
        int i1 = 0; float m1 = v[0];
#pragma unroll
        for (int e = 1; e < E_; e++) if (v[e] > m1) { m1 = v[e]; i1 = e; }
        int i2 = -1; float m2 = -1e30f;
#pragma unroll
        for (int e = 0; e < E_; e++) if (e != i1 && v[e] > m2) { m2 = v[e]; i2 = e; }
        float w0 = 1.f / (1.f + __expf(m2 - m1));
        g_topi[2 * t]     = i1;
        g_topi[2 * t + 1] = i2;
        g_topw[2 * t]     = w0;
        g_topw[2 * t + 1] = 1.f - w0;
    }
    __syncthreads();
    // phase 2: each warp owns one expert; stable prefix count == jax stable argsort
    int wid = tid >> 5, lane = tid & 31;
    if (wid < E_) {
        int e = wid;
        int base = 0;
        for (int j0 = 0; j0 < TK_; j0 += 32) {
            int j = j0 + lane;
            int rid = g_topi[j];
            unsigned m = __ballot_sync(0xffffffffu, rid == e);
            if (rid == e) {
                int p = base + __popc(m & ((1u << lane) - 1u));
                if (p < C_) {
                    g_slot_tok[e * C_ + p] = j >> 1;
                    g_slot_of_j[j] = e * C_ + p;
                } else {
                    g_slot_of_j[j] = -1;
                }
            }
            base += __popc(m);
        }
        if (lane == 0) g_cnt[e] = base < C_ ? base : C_;
    }
}

// ---------------- GEMM1 (fused gather + gate/up + SiLU) --------------------
// out tile: 128 rows x 64 cols of I; A = gathered x rows; B = w13[e] (gate&up)
__global__ __launch_bounds__(256, 2) void gemm1_kernel(const float* __restrict__ x,
                                                       const float* __restrict__ w13) {
    const int e    = blockIdx.y >> 2;
    const int row0 = (blockIdx.y & 3) << 7;   // 128-row tiles within capacity
    const int cnt  = g_cnt[e];
    if (row0 >= cnt) return;                  // skip empty capacity tiles
    const int n0 = blockIdx.x << 6;           // 64-col tile of I

    __shared__ float As[16][128];
    __shared__ float Bg[16][64];
    __shared__ float Bu[16][64];

    const int tid   = threadIdx.x;
    const int lrowA = tid >> 1, lk8 = (tid & 1) << 3;
    const int lrowB = tid >> 2, lk4 = (tid & 3) << 2;

    const float* ap = nullptr;
    {
        int rg = row0 + lrowA;
        if (rg < cnt) ap = x + (size_t)g_slot_tok[e * C_ + rg] * H_ + lk8;
    }
    const float* gp = w13 + (size_t)e * 2 * I_ * H_ + (size_t)(n0 + lrowB) * H_ + lk4;
    const float* up = gp + (size_t)I_ * H_;

    const int tx = tid & 15, ty = tid >> 4;

    float accg[8][4], accu[8][4];
#pragma unroll
    for (int i = 0; i < 8; i++)
#pragma unroll
        for (int j = 0; j < 4; j++) { accg[i][j] = 0.f; accu[i][j] = 0.f; }

    for (int k0 = 0; k0 < H_; k0 += 16) {
        float4 a0 = ap ? *(const float4*)(ap + k0)     : make_float4(0, 0, 0, 0);
        float4 a1 = ap ? *(const float4*)(ap + k0 + 4) : make_float4(0, 0, 0, 0);
        float4 gv = *(const float4*)(gp + k0);
        float4 uv = *(const float4*)(up + k0);
        __syncthreads();
        As[lk8 + 0][lrowA] = a0.x; As[lk8 + 1][lrowA] = a0.y;
        As[lk8 + 2][lrowA] = a0.z; As[lk8 + 3][lrowA] = a0.w;
        As[lk8 + 4][lrowA] = a1.x; As[lk8 + 5][lrowA] = a1.y;
        As[lk8 + 6][lrowA] = a1.z; As[lk8 + 7][lrowA] = a1.w;
        Bg[lk4 + 0][lrowB] = gv.x; Bg[lk4 + 1][lrowB] = gv.y;
        Bg[lk4 + 2][lrowB] = gv.z; Bg[lk4 + 3][lrowB] = gv.w;
        Bu[lk4 + 0][lrowB] = uv.x; Bu[lk4 + 1][lrowB] = uv.y;
        Bu[lk4 + 2][lrowB] = uv.z; Bu[lk4 + 3][lrowB] = uv.w;
        __syncthreads();
#pragma unroll
        for (int kk = 0; kk < 16; kk++) {
            float4 aL = *(const float4*)&As[kk][ty * 8];
            float4 aH = *(const float4*)&As[kk][ty * 8 + 4];
            float4 bg = *(const float4*)&Bg[kk][tx * 4];
            float4 bu = *(const float4*)&Bu[kk][tx * 4];
            float av[8]  = {aL.x, aL.y, aL.z, aL.w, aH.x, aH.y, aH.z, aH.w};
            float bgv[4] = {bg.x, bg.y, bg.z, bg.w};
            float buv[4] = {bu.x, bu.y, bu.z, bu.w};
#pragma unroll
            for (int i = 0; i < 8; i++)
#pragma unroll
                for (int j = 0; j < 4; j++) {
                    accg[i][j] += av[i] * bgv[j];
                    accu[i][j] += av[i] * buv[j];
                }
        }
    }
    // epilogue: act = silu(gate) * up
#pragma unroll
    for (int i = 0; i < 8; i++) {
        int r = row0 + ty * 8 + i;
        if (r < cnt) {
            float o[4];
#pragma unroll
            for (int j = 0; j < 4; j++) {
                float g = accg[i][j];
                float s = g / (1.f + __expf(-g));
                o[j] = s * accu[i][j];
            }
            *(float4*)(g_act + ((size_t)e * C_ + r) * I_ + n0 + tx * 4) =
                make_float4(o[0], o[1], o[2], o[3]);
        }
    }
}

// ---------------- GEMM2: ybuf = act @ w2[e]^T ------------------------------
__global__ __launch_bounds__(256, 2) void gemm2_kernel(const float* __restrict__ w2) {
    const int e    = blockIdx.y >> 2;
    const int row0 = (blockIdx.y & 3) << 7;
    const int cnt  = g_cnt[e];
    if (row0 >= cnt) return;
    const int n0 = blockIdx.x << 6;           // 64-col tile of H

    __shared__ float As[16][128];
    __shared__ float Bs[16][64];

    const int tid   = threadIdx.x;
    const int lrowA = tid >> 1, lk8 = (tid & 1) << 3;
    const int lrowB = tid >> 2, lk4 = (tid & 3) << 2;

    const float* ap = g_act + ((size_t)e * C_ + row0 + lrowA) * I_ + lk8;
    const float* bp = w2 + (size_t)e * H_ * I_ + (size_t)(n0 + lrowB) * I_ + lk4;

    const int tx = tid & 15, ty = tid >> 4;

    float acc[8][4];
#pragma unroll
    for (int i = 0; i < 8; i++)
#pragma unroll
        for (int j = 0; j < 4; j++) acc[i][j] = 0.f;

    for (int k0 = 0; k0 < I_; k0 += 16) {
        float4 a0 = *(const float4*)(ap + k0);
        float4 a1 = *(const float4*)(ap + k0 + 4);
        float4 bv = *(const float4*)(bp + k0);
        __syncthreads();
        As[lk8 + 0][lrowA] = a0.x; As[lk8 + 1][lrowA] = a0.y;
        As[lk8 + 2][lrowA] = a0.z; As[lk8 + 3][lrowA] = a0.w;
        As[lk8 + 4][lrowA] = a1.x; As[lk8 + 5][lrowA] = a1.y;
        As[lk8 + 6][lrowA] = a1.z; As[lk8 + 7][lrowA] = a1.w;
        Bs[lk4 + 0][lrowB] = bv.x; Bs[lk4 + 1][lrowB] = bv.y;
        Bs[lk4 + 2][lrowB] = bv.z; Bs[lk4 + 3][lrowB] = bv.w;
        __syncthreads();
#pragma unroll
        for (int kk = 0; kk < 16; kk++) {
            float4 aL = *(const float4*)&As[kk][ty * 8];
            float4 aH = *(const float4*)&As[kk][ty * 8 + 4];
            float4 bv4 = *(const float4*)&Bs[kk][tx * 4];
            float av[8] = {aL.x, aL.y, aL.z, aL.w, aH.x, aH.y, aH.z, aH.w};
            float bb[4] = {bv4.x, bv4.y, bv4.z, bv4.w};
#pragma unroll
            for (int i = 0; i < 8; i++)
#pragma unroll
                for (int j = 0; j < 4; j++) acc[i][j] += av[i] * bb[j];
        }
    }
#pragma unroll
    for (int i = 0; i < 8; i++) {
        int r = row0 + ty * 8 + i;
        if (r < cnt) {
            *(float4*)(g_ybuf + ((size_t)e * C_ + r) * H_ + n0 + tx * 4) =
                make_float4(acc[i][0], acc[i][1], acc[i][2], acc[i][3]);
        }
    }
}

// ---------------- combine: out[t] = w0*y[slot0] + w1*y[slot1] --------------
__global__ void combine_kernel(float* __restrict__ out) {
    int idx = blockIdx.x * blockDim.x + threadIdx.x;
    if (idx >= T_ * H_ / 4) return;
    int t = idx >> 9;            // H/4 = 512 float4s per token
    int h = (idx & 511) << 2;
    float w0 = g_topw[2 * t], w1 = g_topw[2 * t + 1];
    int s0 = g_slot_of_j[2 * t], s1 = g_slot_of_j[2 * t + 1];
    float4 r = make_float4(0, 0, 0, 0);
    if (s0 >= 0) {
        float4 v = *(const float4*)(g_ybuf + (size_t)s0 * H_ + h);
        r.x += w0 * v.x; r.y += w0 * v.y; r.z += w0 * v.z; r.w += w0 * v.w;
    }
    if (s1 >= 0) {
        float4 v = *(const float4*)(g_ybuf + (size_t)s1 * H_ + h);
        r.x += w1 * v.x; r.y += w1 * v.y; r.z += w1 * v.z; r.w += w1 * v.w;
    }
    *(float4*)(out + (size_t)t * H_ + h) = r;
}

// ---------------- launch ----------------------------------------------------
extern "C" void kernel_launch(void* const* d_in, const int* in_sizes, int n_in,
                              void* d_out, int out_size) {
    const float* x      = (const float*)d_in[0];
    const float* logits = (const float*)d_in[1];
    const float* w13    = (const float*)d_in[2];
    const float* w2     = (const float*)d_in[3];
    float* out          = (float*)d_out;

    router_kernel<<<1, 512>>>(logits);
    // GEMM1: 22 N-tiles (I/64) x 64 row-tiles (E * C/128)
    gemm1_kernel<<<dim3(I_ / 64, E_ * (C_ / 128)), 256>>>(x, w13);
    // GEMM2: 32 N-tiles (H/64) x 64 row-tiles
    gemm2_kernel<<<dim3(H_ / 64, E_ * (C_ / 128)), 256>>>(w2);
    combine_kernel<<<(T_ * H_ / 4 + 255) / 256, 256>>>(out);
}

// round 3
// speedup vs baseline: 1.3600x; 1.3600x over previous
#include <cuda_runtime.h>
#include <cuda_bf16.h>
#include <cstdint>

#define T_  1024
#define H_  2048
#define I_  1408
#define E_  16
#define C_  512
#define TK_ 2048

// ---------------- scratch (device globals) ---------------------------------
__device__ int   g_topi[TK_];
__device__ float g_topw[TK_];
__device__ int   g_slot_tok[E_ * C_];
__device__ int   g_slot_of_j[TK_];
__device__ int   g_cnt[E_];
__device__ __nv_bfloat16 g_xb_hi[(size_t)E_ * C_ * H_];
__device__ __nv_bfloat16 g_xb_lo[(size_t)E_ * C_ * H_];
__device__ __nv_bfloat16 g_act_hi[(size_t)E_ * C_ * I_];
__device__ __nv_bfloat16 g_act_lo[(size_t)E_ * C_ * I_];
__device__ float g_ybuf[(size_t)E_ * C_ * H_];

// ---------------- helpers ----------------------------------------------------
__device__ __forceinline__ uint32_t smem_u32(const void* p) {
    return (uint32_t)__cvta_generic_to_shared(p);
}
static __device__ __forceinline__ void ldsm_x4(uint32_t addr, uint32_t r[4]) {
    asm volatile("ldmatrix.sync.aligned.m8n8.x4.shared.b16 {%0,%1,%2,%3},[%4];"
                 : "=r"(r[0]), "=r"(r[1]), "=r"(r[2]), "=r"(r[3]) : "r"(addr));
}
static __device__ __forceinline__ void mma16816(float d[4], const uint32_t a[4],
                                                uint32_t b0, uint32_t b1) {
    asm volatile(
        "mma.sync.aligned.m16n8k16.row.col.f32.bf16.bf16.f32 "
        "{%0,%1,%2,%3},{%4,%5,%6,%7},{%8,%9},{%0,%1,%2,%3};"
        : "+f"(d[0]), "+f"(d[1]), "+f"(d[2]), "+f"(d[3])
        : "r"(a[0]), "r"(a[1]), "r"(a[2]), "r"(a[3]), "r"(b0), "r"(b1));
}
static __device__ __forceinline__ void split2(float f0, float f1, uint32_t& hi, uint32_t& lo) {
    __nv_bfloat16 h0 = __float2bfloat16_rn(f0);
    __nv_bfloat16 h1 = __float2bfloat16_rn(f1);
    __nv_bfloat16 l0 = __float2bfloat16_rn(f0 - __bfloat162float(h0));
    __nv_bfloat16 l1 = __float2bfloat16_rn(f1 - __bfloat162float(h1));
    hi = ((uint32_t)__bfloat16_as_ushort(h1) << 16) | __bfloat16_as_ushort(h0);
    lo = ((uint32_t)__bfloat16_as_ushort(l1) << 16) | __bfloat16_as_ushort(l0);
}

// SMEM tile geometry: rows padded to 80B (64B data + 16B) -> conflict-free LDSM
#define ROWB      80
#define PLANE_SZ  (128 * ROWB)          // 10240
#define STAGE_SZ  (4 * PLANE_SZ)        // A_hi, A_lo, B_hi, B_lo
#define A_HI 0
#define A_LO PLANE_SZ
#define B_HI (2 * PLANE_SZ)
#define B_LO (3 * PLANE_SZ)
#define SMEM_TOTAL (2 * STAGE_SZ)       // 81920

// ---------------- routing ---------------------------------------------------
__global__ void router_kernel(const float* __restrict__ logits) {
    int tid = threadIdx.x;
    for (int t = tid; t < T_; t += 512) {
        const float* l = logits + t * E_;
        float v[E_];
#pragma unroll
        for (int e = 0; e < E_; e++) v[e] = l[e];
        int i1 = 0; float m1 = v[0];
#pragma unroll
        for (int e = 1; e < E_; e++) if (v[e] > m1) { m1 = v[e]; i1 = e; }
        int i2 = -1; float m2 = -1e30f;
#pragma unroll
        for (int e = 0; e < E_; e++) if (e != i1 && v[e] > m2) { m2 = v[e]; i2 = e; }
        float w0 = 1.f / (1.f + __expf(m2 - m1));
        g_topi[2 * t] = i1; g_topi[2 * t + 1] = i2;
        g_topw[2 * t] = w0; g_topw[2 * t + 1] = 1.f - w0;
    }
    __syncthreads();
    int wid = tid >> 5, lane = tid & 31;
    if (wid < E_) {
        int e = wid, base = 0;
        for (int j0 = 0; j0 < TK_; j0 += 32) {
            int j = j0 + lane;
            int rid = g_topi[j];
            unsigned m = __ballot_sync(0xffffffffu, rid == e);
            if (rid == e) {
                int p = base + __popc(m & ((1u << lane) - 1u));
                if (p < C_) {
                    g_slot_tok[e * C_ + p] = j >> 1;
                    g_slot_of_j[j] = e * C_ + p;
                } else g_slot_of_j[j] = -1;
            }
            base += __popc(m);
        }
        if (lane == 0) g_cnt[e] = base < C_ ? base : C_;
    }
}

// ---------------- prepass: gather x rows, split into bf16 hi/lo -------------
__global__ __launch_bounds__(256) void prepass_kernel(const float* __restrict__ x) {
    int e = blockIdx.x >> 2, row0 = (blockIdx.x & 3) << 7;
    int cnt = g_cnt[e];
    if (row0 >= cnt) return;
    int wid = threadIdx.x >> 5, lane = threadIdx.x & 31;
    for (int r = row0 + wid; r < row0 + 128; r += 8) {
        bool v = r < cnt;
        const float* src = v ? x + (size_t)g_slot_tok[e * C_ + r] * H_ : nullptr;
        size_t dst = (size_t)(e * C_ + r) * H_;
        for (int k = lane * 4; k < H_; k += 128) {
            float4 f = v ? *(const float4*)(src + k) : make_float4(0, 0, 0, 0);
            uint32_t h0, l0, h1, l1;
            split2(f.x, f.y, h0, l0);
            split2(f.z, f.w, h1, l1);
            *(uint2*)(g_xb_hi + dst + k) = make_uint2(h0, h1);
            *(uint2*)(g_xb_lo + dst + k) = make_uint2(l0, l1);
        }
    }
}

// ---------------- gmem->reg loaders + reg->smem stores -----------------------
struct ARegs { uint4 v[4]; };
struct BRegs { float4 v[4]; };

static __device__ __forceinline__ void ldA(ARegs& R, const __nv_bfloat16* ahi,
                                           const __nv_bfloat16* alo, int Kdim, int k0,
                                           int tid) {
#pragma unroll
    for (int i = 0; i < 4; i++) {
        int id = tid + 256 * i;
        int plane = id >> 9, rem = id & 511;
        int row = rem >> 2, c = rem & 3;
        const __nv_bfloat16* src = (plane ? alo : ahi) + (size_t)row * Kdim + k0 + c * 8;
        R.v[i] = *(const uint4*)src;
    }
}
static __device__ __forceinline__ void stA(const ARegs& R, uint32_t sst, int tid) {
#pragma unroll
    for (int i = 0; i < 4; i++) {
        int id = tid + 256 * i;
        int plane = id >> 9, rem = id & 511;
        int row = rem >> 2, c = rem & 3;
        uint32_t dst = sst + (plane ? A_LO : A_HI) + row * ROWB + c * 16;
        asm volatile("st.shared.v4.b32 [%0],{%1,%2,%3,%4};" ::"r"(dst), "r"(R.v[i].x),
                     "r"(R.v[i].y), "r"(R.v[i].z), "r"(R.v[i].w));
    }
}
template <typename F>
static __device__ __forceinline__ void ldB(BRegs& R, F rowptr, int k0, int tid) {
#pragma unroll
    for (int i = 0; i < 4; i++) {
        int id = tid + 256 * i;
        int row = id >> 3, c = id & 7;
        R.v[i] = *(const float4*)(rowptr(row) + k0 + c * 4);
    }
}
static __device__ __forceinline__ void stB(const BRegs& R, uint32_t sst, int tid) {
#pragma unroll
    for (int i = 0; i < 4; i++) {
        int id = tid + 256 * i;
        int row = id >> 3, c = id & 7;
        uint32_t h0, l0, h1, l1;
        split2(R.v[i].x, R.v[i].y, h0, l0);
        split2(R.v[i].z, R.v[i].w, h1, l1);
        uint32_t off = row * ROWB + c * 8;
        asm volatile("st.shared.v2.b32 [%0],{%1,%2};" ::"r"(sst + B_HI + off), "r"(h0), "r"(h1));
        asm volatile("st.shared.v2.b32 [%0],{%1,%2};" ::"r"(sst + B_LO + off), "r"(l0), "r"(l1));
    }
}

// ---------------- warp mma over one smem stage -------------------------------
static __device__ __forceinline__ void mma_stage(uint32_t sst, int mbase, int nbase,
                                                 int lane, float acc[2][8][4]) {
    int a_row = lane & 15, a_kh = lane >> 4;
    int b_mat = lane >> 3, b_r = lane & 7;
    int b_radd = (b_mat & 2) ? 8 : 0, b_kh = b_mat & 1;
#pragma unroll
    for (int k16 = 0; k16 < 2; k16++) {
        uint32_t ah[2][4], al[2][4];
#pragma unroll
        for (int mt = 0; mt < 2; mt++) {
            uint32_t ao = (mbase + mt * 16 + a_row) * ROWB + k16 * 32 + a_kh * 16;
            ldsm_x4(sst + A_HI + ao, ah[mt]);
            ldsm_x4(sst + A_LO + ao, al[mt]);
        }
#pragma unroll
        for (int pj = 0; pj < 4; pj++) {
            uint32_t bh[4], bl[4];
            uint32_t bo = (nbase + pj * 16 + b_radd + b_r) * ROWB + k16 * 32 + b_kh * 16;
            ldsm_x4(sst + B_HI + bo, bh);
            ldsm_x4(sst + B_LO + bo, bl);
#pragma unroll
            for (int t = 0; t < 2; t++) {
                int nt = 2 * pj + t;
#pragma unroll
                for (int mt = 0; mt < 2; mt++) {
                    mma16816(acc[mt][nt], ah[mt], bh[2 * t], bh[2 * t + 1]);
                    mma16816(acc[mt][nt], ah[mt], bl[2 * t], bl[2 * t + 1]);
                    mma16816(acc[mt][nt], al[mt], bh[2 * t], bh[2 * t + 1]);
                }
            }
        }
    }
}

// ---------------- GEMM1: xbuf @ w13^T (gate/up interleaved), SiLU -> act -----
__global__ __launch_bounds__(256, 1) void gemm1_mma(const float* __restrict__ w13) {
    extern __shared__ char smem[];
    const int e = blockIdx.y >> 2;
    const int row0 = (blockIdx.y & 3) << 7;
    const int cnt = g_cnt[e];
    if (row0 >= cnt) return;
    const int n0 = blockIdx.x << 6;   // 64 I-cols
    const int tid = threadIdx.x;
    const int lane = tid & 31, wid = tid >> 5;
    const int mbase = (wid & 3) * 32, nbase = (wid >> 2) * 64;
    uint32_t sb = smem_u32(smem);

    const __nv_bfloat16* ahi = g_xb_hi + (size_t)(e * C_ + row0) * H_;
    const __nv_bfloat16* alo = g_xb_lo + (size_t)(e * C_ + row0) * H_;
    const float* wbase = w13 + (size_t)e * 2 * I_ * H_;
    auto rowptr = [&](int rb) {
        int grow = (rb & 1) ? (I_ + n0 + (rb >> 1)) : (n0 + (rb >> 1));
        return wbase + (size_t)grow * H_;
    };

    float acc[2][8][4];
#pragma unroll
    for (int a = 0; a < 2; a++)
#pragma unroll
        for (int b = 0; b < 8; b++)
#pragma unroll
            for (int c = 0; c < 4; c++) acc[a][b][c] = 0.f;

    const int NCH = H_ / 32;  // 64
    ARegs ar; BRegs br;
    ldA(ar, ahi, alo, H_, 0, tid);
    ldB(br, rowptr, 0, tid);
    stA(ar, sb, tid); stB(br, sb, tid);
    __syncthreads();
    for (int c = 0; c < NCH; c++) {
        if (c + 1 < NCH) {
            ldA(ar, ahi, alo, H_, (c + 1) * 32, tid);
            ldB(br, rowptr, (c + 1) * 32, tid);
        }
        mma_stage(sb + (c & 1) * STAGE_SZ, mbase, nbase, lane, acc);
        if (c + 1 < NCH) {
            uint32_t sst = sb + ((c + 1) & 1) * STAGE_SZ;
            stA(ar, sst, tid); stB(br, sst, tid);
        }
        __syncthreads();
    }

    // epilogue: c-pair (even,odd) = (gate, up) for one I-col
#pragma unroll
    for (int mt = 0; mt < 2; mt++) {
#pragma unroll
        for (int half = 0; half < 2; half++) {
            int r = row0 + mbase + mt * 16 + (lane >> 2) + half * 8;
            if (r < cnt) {
                size_t ob = (size_t)(e * C_ + r) * I_;
#pragma unroll
                for (int nt = 0; nt < 8; nt++) {
                    int cn = nbase + nt * 8 + (lane & 3) * 2;
                    int icol = n0 + (cn >> 1);
                    float g = acc[mt][nt][2 * half];
                    float u = acc[mt][nt][2 * half + 1];
                    float a = g / (1.f + __expf(-g)) * u;
                    __nv_bfloat16 hi = __float2bfloat16_rn(a);
                    __nv_bfloat16 lo = __float2bfloat16_rn(a - __bfloat162float(hi));
                    g_act_hi[ob + icol] = hi;
                    g_act_lo[ob + icol] = lo;
                }
            }
        }
    }
}

// ---------------- GEMM2: act @ w2^T -> ybuf (fp32) ---------------------------
__global__ __launch_bounds__(256, 1) void gemm2_mma(const float* __restrict__ w2) {
    extern __shared__ char smem[];
    const int e = blockIdx.y >> 2;
    const int row0 = (blockIdx.y & 3) << 7;
    const int cnt = g_cnt[e];
    if (row0 >= cnt) return;
    const int n0 = blockIdx.x << 7;   // 128 H-cols
    const int tid = threadIdx.x;
    const int lane = tid & 31, wid = tid >> 5;
    const int mbase = (wid & 3) * 32, nbase = (wid >> 2) * 64;
    uint32_t sb = smem_u32(smem);

    const __nv_bfloat16* ahi = g_act_hi + (size_t)(e * C_ + row0) * I_;
    const __nv_bfloat16* alo = g_act_lo + (size_t)(e * C_ + row0) * I_;
    const float* wbase = w2 + (size_t)e * H_ * I_;
    auto rowptr = [&](int rb) { return wbase + (size_t)(n0 + rb) * I_; };

    float acc[2][8][4];
#pragma unroll
    for (int a = 0; a < 2; a++)
#pragma unroll
        for (int b = 0; b < 8; b++)
#pragma unroll
            for (int c = 0; c < 4; c++) acc[a][b][c] = 0.f;

    const int NCH = I_ / 32;  // 44
    ARegs ar; BRegs br;
    ldA(ar, ahi, alo, I_, 0, tid);
    ldB(br, rowptr, 0, tid);
    stA(ar, sb, tid); stB(br, sb, tid);
    __syncthreads();
    for (int c = 0; c < NCH; c++) {
        if (c + 1 < NCH) {
            ldA(ar, ahi, alo, I_, (c + 1) * 32, tid);
            ldB(br, rowptr, (c + 1) * 32, tid);
        }
        mma_stage(sb + (c & 1) * STAGE_SZ, mbase, nbase, lane, acc);
        if (c + 1 < NCH) {
            uint32_t sst = sb + ((c + 1) & 1) * STAGE_SZ;
            stA(ar, sst, tid); stB(br, sst, tid);
        }
        __syncthreads();
    }

#pragma unroll
    for (int mt = 0; mt < 2; mt++) {
#pragma unroll
        for (int half = 0; half < 2; half++) {
            int r = row0 + mbase + mt * 16 + (lane >> 2) + half * 8;
            if (r < cnt) {
                float* ob = g_ybuf + (size_t)(e * C_ + r) * H_ + n0;
#pragma unroll
                for (int nt = 0; nt < 8; nt++) {
                    int col = nbase + nt * 8 + (lane & 3) * 2;
                    *(float2*)(ob + col) =
                        make_float2(acc[mt][nt][2 * half], acc[mt][nt][2 * half + 1]);
                }
            }
        }
    }
}

// ---------------- combine ----------------------------------------------------
__global__ void combine_kernel(float* __restrict__ out) {
    int idx = blockIdx.x * blockDim.x + threadIdx.x;
    if (idx >= T_ * H_ / 4) return;
    int t = idx >> 9;
    int h = (idx & 511) << 2;
    float w0 = g_topw[2 * t], w1 = g_topw[2 * t + 1];
    int s0 = g_slot_of_j[2 * t], s1 = g_slot_of_j[2 * t + 1];
    float4 r = make_float4(0, 0, 0, 0);
    if (s0 >= 0) {
        float4 v = *(const float4*)(g_ybuf + (size_t)s0 * H_ + h);
        r.x += w0 * v.x; r.y += w0 * v.y; r.z += w0 * v.z; r.w += w0 * v.w;
    }
    if (s1 >= 0) {
        float4 v = *(const float4*)(g_ybuf + (size_t)s1 * H_ + h);
        r.x += w1 * v.x; r.y += w1 * v.y; r.z += w1 * v.z; r.w += w1 * v.w;
    }
    *(float4*)(out + (size_t)t * H_ + h) = r;
}

// ---------------- launch ----------------------------------------------------
extern "C" void kernel_launch(void* const* d_in, const int* in_sizes, int n_in,
                              void* d_out, int out_size) {
    const float* x      = (const float*)d_in[0];
    const float* logits = (const float*)d_in[1];
    const float* w13    = (const float*)d_in[2];
    const float* w2     = (const float*)d_in[3];
    float* out          = (float*)d_out;

    static int smem_set = 0;
    if (!smem_set) {
        cudaFuncSetAttribute(gemm1_mma, cudaFuncAttributeMaxDynamicSharedMemorySize, SMEM_TOTAL);
        cudaFuncSetAttribute(gemm2_mma, cudaFuncAttributeMaxDynamicSharedMemorySize, SMEM_TOTAL);
        smem_set = 1;
    }

    router_kernel<<<1, 512>>>(logits);
    prepass_kernel<<<E_ * (C_ / 128), 256>>>(x);
    gemm1_mma<<<dim3(I_ / 64, E_ * (C_ / 128)), 256, SMEM_TOTAL>>>(w13);
    gemm2_mma<<<dim3(H_ / 128, E_ * (C_ / 128)), 256, SMEM_TOTAL>>>(w2);
    combine_kernel<<<(T_ * H_ / 4 + 255) / 256, 256>>>(out);
}

// round 4
// speedup vs baseline: 2.2429x; 1.6493x over previous
#include <cuda_runtime.h>
#include <cuda_bf16.h>
#include <cstdint>

#define T_  1024
#define H_  2048
#define I_  1408
#define E_  16
#define C_  512
#define TK_ 2048

// ---------------- scratch (device globals) ---------------------------------
__device__ int   g_topi[TK_];
__device__ float g_topw[TK_];
__device__ int   g_slot_tok[E_ * C_];
__device__ int   g_slot_of_j[TK_];
__device__ int   g_cnt[E_];
__device__ __align__(16) __nv_bfloat16 g_xb_hi[(size_t)E_ * C_ * H_];
__device__ __align__(16) __nv_bfloat16 g_xb_lo[(size_t)E_ * C_ * H_];
__device__ __align__(16) __nv_bfloat16 g_act_hi[(size_t)E_ * C_ * I_];
__device__ __align__(16) __nv_bfloat16 g_act_lo[(size_t)E_ * C_ * I_];
__device__ float g_ybuf[(size_t)E_ * C_ * H_];

// ---------------- helpers ----------------------------------------------------
__device__ __forceinline__ uint32_t smem_u32(const void* p) {
    return (uint32_t)__cvta_generic_to_shared(p);
}
static __device__ __forceinline__ void ldsm_x4(uint32_t addr, uint32_t r[4]) {
    asm volatile("ldmatrix.sync.aligned.m8n8.x4.shared.b16 {%0,%1,%2,%3},[%4];"
                 : "=r"(r[0]), "=r"(r[1]), "=r"(r[2]), "=r"(r[3]) : "r"(addr));
}
static __device__ __forceinline__ void mma16816(float d[4], const uint32_t a[4],
                                                uint32_t b0, uint32_t b1) {
    asm volatile(
        "mma.sync.aligned.m16n8k16.row.col.f32.bf16.bf16.f32 "
        "{%0,%1,%2,%3},{%4,%5,%6,%7},{%8,%9},{%0,%1,%2,%3};"
        : "+f"(d[0]), "+f"(d[1]), "+f"(d[2]), "+f"(d[3])
        : "r"(a[0]), "r"(a[1]), "r"(a[2]), "r"(a[3]), "r"(b0), "r"(b1));
}
static __device__ __forceinline__ void split2(float f0, float f1, uint32_t& hi, uint32_t& lo) {
    __nv_bfloat16 h0 = __float2bfloat16_rn(f0);
    __nv_bfloat16 h1 = __float2bfloat16_rn(f1);
    __nv_bfloat16 l0 = __float2bfloat16_rn(f0 - __bfloat162float(h0));
    __nv_bfloat16 l1 = __float2bfloat16_rn(f1 - __bfloat162float(h1));
    hi = ((uint32_t)__bfloat16_as_ushort(h1) << 16) | __bfloat16_as_ushort(h0);
    lo = ((uint32_t)__bfloat16_as_ushort(l1) << 16) | __bfloat16_as_ushort(l0);
}
static __device__ __forceinline__ void cp16(uint32_t dst, const void* src) {
    asm volatile("cp.async.ca.shared.global [%0],[%1],16;" ::"r"(dst), "l"(src));
}
static __device__ __forceinline__ void cp_commit() {
    asm volatile("cp.async.commit_group;" ::: "memory");
}
static __device__ __forceinline__ void cp_wait0() {
    asm volatile("cp.async.wait_group 0;" ::: "memory");
}
static __device__ __forceinline__ void mbar_init(uint32_t a, uint32_t cnt) {
    asm volatile("mbarrier.init.shared.b64 [%0], %1;" ::"r"(a), "r"(cnt) : "memory");
}
static __device__ __forceinline__ void mbar_arrive(uint32_t a) {
    asm volatile("mbarrier.arrive.shared.b64 _, [%0];" ::"r"(a) : "memory");
}
static __device__ __forceinline__ void mbar_wait(uint32_t a, uint32_t parity) {
    uint32_t done = 0;
    while (!done) {
        asm volatile(
            "{\n\t.reg .pred p;\n\t"
            "mbarrier.try_wait.parity.acquire.cta.shared::cta.b64 p, [%1], %2, 0x989680;\n\t"
            "selp.b32 %0,1,0,p;\n\t}"
            : "=r"(done) : "r"(a), "r"(parity) : "memory");
    }
}

// SMEM tile geometry: rows padded to 80B (64B data + 16B) -> conflict-free LDSM
#define ROWB      80
#define PLANE_SZ  (128 * ROWB)          // 10240
#define STAGE_SZ  (4 * PLANE_SZ)        // 40960: A_hi, A_lo, B_hi, B_lo
#define A_HI 0
#define A_LO PLANE_SZ
#define B_HI (2 * PLANE_SZ)
#define B_LO (3 * PLANE_SZ)
#define NSTAGE 4
#define BAR_OFF (NSTAGE * STAGE_SZ)     // 163840
#define SMEM_TOTAL (BAR_OFF + 128)

// ---------------- routing ---------------------------------------------------
__global__ void router_kernel(const float* __restrict__ logits) {
    int tid = threadIdx.x;
    for (int t = tid; t < T_; t += 512) {
        const float* l = logits + t * E_;
        float v[E_];
#pragma unroll
        for (int e = 0; e < E_; e++) v[e] = l[e];
        int i1 = 0; float m1 = v[0];
#pragma unroll
        for (int e = 1; e < E_; e++) if (v[e] > m1) { m1 = v[e]; i1 = e; }
        int i2 = -1; float m2 = -1e30f;
#pragma unroll
        for (int e = 0; e < E_; e++) if (e != i1 && v[e] > m2) { m2 = v[e]; i2 = e; }
        float w0 = 1.f / (1.f + __expf(m2 - m1));
        g_topi[2 * t] = i1; g_topi[2 * t + 1] = i2;
        g_topw[2 * t] = w0; g_topw[2 * t + 1] = 1.f - w0;
    }
    __syncthreads();
    int wid = tid >> 5, lane = tid & 31;
    if (wid < E_) {
        int e = wid, base = 0;
        for (int j0 = 0; j0 < TK_; j0 += 32) {
            int j = j0 + lane;
            int rid = g_topi[j];
            unsigned m = __ballot_sync(0xffffffffu, rid == e);
            if (rid == e) {
                int p = base + __popc(m & ((1u << lane) - 1u));
                if (p < C_) {
                    g_slot_tok[e * C_ + p] = j >> 1;
                    g_slot_of_j[j] = e * C_ + p;
                } else g_slot_of_j[j] = -1;
            }
            base += __popc(m);
        }
        if (lane == 0) g_cnt[e] = base < C_ ? base : C_;
    }
}

// ---------------- prepass: gather x rows, split into bf16 hi/lo -------------
__global__ __launch_bounds__(256) void prepass_kernel(const float* __restrict__ x) {
    int e = blockIdx.x >> 2, row0 = (blockIdx.x & 3) << 7;
    int cnt = g_cnt[e];
    if (row0 >= cnt) return;
    int k0 = blockIdx.y * (H_ / 4);   // 512-col slab
    int wid = threadIdx.x >> 5, lane = threadIdx.x & 31;
    for (int r = row0 + wid; r < row0 + 128; r += 8) {
        bool v = r < cnt;
        const float* src = v ? x + (size_t)g_slot_tok[e * C_ + r] * H_ : nullptr;
        size_t dst = (size_t)(e * C_ + r) * H_;
        for (int k = k0 + lane * 4; k < k0 + H_ / 4; k += 128) {
            float4 f = v ? *(const float4*)(src + k) : make_float4(0, 0, 0, 0);
            uint32_t h0, l0, h1, l1;
            split2(f.x, f.y, h0, l0);
            split2(f.z, f.w, h1, l1);
            *(uint2*)(g_xb_hi + dst + k) = make_uint2(h0, h1);
            *(uint2*)(g_xb_lo + dst + k) = make_uint2(l0, l1);
        }
    }
}

// ---------------- consumer mma over one smem stage ---------------------------
static __device__ __forceinline__ void mma_stage(uint32_t sst, int mbase, int nbase,
                                                 int lane, float acc[2][8][4]) {
    int a_row = lane & 15, a_kh = lane >> 4;
    int b_mat = lane >> 3, b_r = lane & 7;
    int b_radd = (b_mat & 2) ? 8 : 0, b_kh = b_mat & 1;
#pragma unroll
    for (int k16 = 0; k16 < 2; k16++) {
        uint32_t ah[2][4], al[2][4];
#pragma unroll
        for (int mt = 0; mt < 2; mt++) {
            uint32_t ao = (mbase + mt * 16 + a_row) * ROWB + k16 * 32 + a_kh * 16;
            ldsm_x4(sst + A_HI + ao, ah[mt]);
            ldsm_x4(sst + A_LO + ao, al[mt]);
        }
#pragma unroll
        for (int pj = 0; pj < 4; pj++) {
            uint32_t bh[4], bl[4];
            uint32_t bo = (nbase + pj * 16 + b_radd + b_r) * ROWB + k16 * 32 + b_kh * 16;
            ldsm_x4(sst + B_HI + bo, bh);
            ldsm_x4(sst + B_LO + bo, bl);
#pragma unroll
            for (int t = 0; t < 2; t++) {
                int nt = 2 * pj + t;
#pragma unroll
                for (int mt = 0; mt < 2; mt++) {
                    mma16816(acc[mt][nt], ah[mt], bh[2 * t], bh[2 * t + 1]);
                    mma16816(acc[mt][nt], ah[mt], bl[2 * t], bl[2 * t + 1]);
                    mma16816(acc[mt][nt], al[mt], bh[2 * t], bh[2 * t + 1]);
                }
            }
        }
    }
}

// ---------------- warp-specialized GEMM body (shared by both GEMMs) ----------
// Producers: 128 threads (tid 256..383). A via cp.async (bf16), B via LDG+split.
// Consumers: 256 threads (tid 0..255), 8 warps of 32x64 output tiles.
template <typename F>
static __device__ __forceinline__ void gemm_ws(uint32_t sb, int NCH, int Kdim,
                                               const __nv_bfloat16* ahi,
                                               const __nv_bfloat16* alo, F rowptr,
                                               float acc[2][8][4]) {
    const int tid = threadIdx.x;
    if (tid == 0) {
#pragma unroll
        for (int s = 0; s < NSTAGE; s++) {
            mbar_init(sb + BAR_OFF + s * 8, 128);        // full: producers arrive
            mbar_init(sb + BAR_OFF + 64 + s * 8, 256);   // empty: consumers arrive
        }
    }
    __syncthreads();

    if (tid < 256) {
        // ---- consumer ----
        const int lane = tid & 31, wid = tid >> 5;
        const int mbase = (wid & 3) * 32, nbase = (wid >> 2) * 64;
        for (int c = 0; c < NCH; c++) {
            int s = c & (NSTAGE - 1), r = c >> 2;
            mbar_wait(sb + BAR_OFF + s * 8, r & 1);
            mma_stage(sb + s * STAGE_SZ, mbase, nbase, lane, acc);
            mbar_arrive(sb + BAR_OFF + 64 + s * 8);
        }
    } else {
        // ---- producer ----
        const int ptid = tid - 256;
        const float* rp = rowptr(ptid);
        float4 breg[8];
#pragma unroll
        for (int q = 0; q < 8; q++) breg[q] = *(const float4*)(rp + q * 4);
        for (int c = 0; c < NCH; c++) {
            int s = c & (NSTAGE - 1), r = c >> 2;
            if (r > 0) mbar_wait(sb + BAR_OFF + 64 + s * 8, (r - 1) & 1);
            uint32_t sst = sb + s * STAGE_SZ;
            // A planes via cp.async: 1024 x 16B granules
#pragma unroll
            for (int j = 0; j < 8; j++) {
                int g = ptid + 128 * j;
                int plane = g >> 9, rem = g & 511, row = rem >> 2, seg = rem & 3;
                const __nv_bfloat16* src =
                    (plane ? alo : ahi) + (size_t)row * Kdim + c * 32 + seg * 8;
                cp16(sst + (plane ? A_LO : A_HI) + row * ROWB + seg * 16, src);
            }
            cp_commit();
            // B: convert this chunk's prefetched regs
            uint32_t h[16], l[16];
#pragma unroll
            for (int q = 0; q < 8; q++) {
                split2(breg[q].x, breg[q].y, h[2 * q], l[2 * q]);
                split2(breg[q].z, breg[q].w, h[2 * q + 1], l[2 * q + 1]);
            }
            uint32_t bh = sst + B_HI + ptid * ROWB;
            uint32_t bl = sst + B_LO + ptid * ROWB;
#pragma unroll
            for (int m = 0; m < 4; m++) {
                asm volatile("st.shared.v4.b32 [%0],{%1,%2,%3,%4};" ::"r"(bh + 16 * m),
                             "r"(h[4 * m]), "r"(h[4 * m + 1]), "r"(h[4 * m + 2]),
                             "r"(h[4 * m + 3]));
                asm volatile("st.shared.v4.b32 [%0],{%1,%2,%3,%4};" ::"r"(bl + 16 * m),
                             "r"(l[4 * m]), "r"(l[4 * m + 1]), "r"(l[4 * m + 2]),
                             "r"(l[4 * m + 3]));
            }
            // prefetch next chunk's B
            if (c + 1 < NCH) {
                const float* np = rp + (c + 1) * 32;
#pragma unroll
                for (int q = 0; q < 8; q++) breg[q] = *(const float4*)(np + q * 4);
            }
            cp_wait0();
            mbar_arrive(sb + BAR_OFF + s * 8);
        }
    }
}

// ---------------- GEMM1: xbuf @ w13^T (gate/up interleaved), SiLU -> act -----
__global__ __launch_bounds__(384, 1) void gemm1_mma(const float* __restrict__ w13) {
    extern __shared__ char smem[];
    const int e = blockIdx.y >> 2;
    const int row0 = (blockIdx.y & 3) << 7;
    const int cnt = g_cnt[e];
    if (row0 >= cnt) return;
    const int n0 = blockIdx.x << 6;   // 64 I-cols
    uint32_t sb = smem_u32(smem);

    const __nv_bfloat16* ahi = g_xb_hi + (size_t)(e * C_ + row0) * H_;
    const __nv_bfloat16* alo = g_xb_lo + (size_t)(e * C_ + row0) * H_;
    const float* wbase = w13 + (size_t)e * 2 * I_ * H_;
    auto rowptr = [&](int rb) {
        int grow = (rb & 1) ? (I_ + n0 + (rb >> 1)) : (n0 + (rb >> 1));
        return wbase + (size_t)grow * H_;
    };

    float acc[2][8][4];
#pragma unroll
    for (int a = 0; a < 2; a++)
#pragma unroll
        for (int b = 0; b < 8; b++)
#pragma unroll
            for (int c = 0; c < 4; c++) acc[a][b][c] = 0.f;

    gemm_ws(sb, H_ / 32, H_, ahi, alo, rowptr, acc);

    const int tid = threadIdx.x;
    if (tid < 256) {
        const int lane = tid & 31, wid = tid >> 5;
        const int mbase = (wid & 3) * 32, nbase = (wid >> 2) * 64;
#pragma unroll
        for (int mt = 0; mt < 2; mt++) {
#pragma unroll
            for (int half = 0; half < 2; half++) {
                int r = row0 + mbase + mt * 16 + (lane >> 2) + half * 8;
                if (r < cnt) {
                    size_t ob = (size_t)(e * C_ + r) * I_;
#pragma unroll
                    for (int nt = 0; nt < 8; nt++) {
                        int cn = nbase + nt * 8 + (lane & 3) * 2;
                        int icol = n0 + (cn >> 1);
                        float g = acc[mt][nt][2 * half];
                        float u = acc[mt][nt][2 * half + 1];
                        float a = g / (1.f + __expf(-g)) * u;
                        __nv_bfloat16 hi = __float2bfloat16_rn(a);
                        __nv_bfloat16 lo = __float2bfloat16_rn(a - __bfloat162float(hi));
                        g_act_hi[ob + icol] = hi;
                        g_act_lo[ob + icol] = lo;
                    }
                }
            }
        }
    }
}

// ---------------- GEMM2: act @ w2^T -> ybuf (fp32) ---------------------------
__global__ __launch_bounds__(384, 1) void gemm2_mma(const float* __restrict__ w2) {
    extern __shared__ char smem[];
    const int e = blockIdx.y >> 2;
    const int row0 = (blockIdx.y & 3) << 7;
    const int cnt = g_cnt[e];
    if (row0 >= cnt) return;
    const int n0 = blockIdx.x << 7;   // 128 H-cols
    uint32_t sb = smem_u32(smem);

    const __nv_bfloat16* ahi = g_act_hi + (size_t)(e * C_ + row0) * I_;
    const __nv_bfloat16* alo = g_act_lo + (size_t)(e * C_ + row0) * I_;
    const float* wbase = w2 + (size_t)e * H_ * I_;
    auto rowptr = [&](int rb) { return wbase + (size_t)(n0 + rb) * I_; };

    float acc[2][8][4];
#pragma unroll
    for (int a = 0; a < 2; a++)
#pragma unroll
        for (int b = 0; b < 8; b++)
#pragma unroll
            for (int c = 0; c < 4; c++) acc[a][b][c] = 0.f;

    gemm_ws(sb, I_ / 32, I_, ahi, alo, rowptr, acc);

    const int tid = threadIdx.x;
    if (tid < 256) {
        const int lane = tid & 31, wid = tid >> 5;
        const int mbase = (wid & 3) * 32, nbase = (wid >> 2) * 64;
#pragma unroll
        for (int mt = 0; mt < 2; mt++) {
#pragma unroll
            for (int half = 0; half < 2; half++) {
                int r = row0 + mbase + mt * 16 + (lane >> 2) + half * 8;
                if (r < cnt) {
                    float* ob = g_ybuf + (size_t)(e * C_ + r) * H_ + n0;
#pragma unroll
                    for (int nt = 0; nt < 8; nt++) {
                        int col = nbase + nt * 8 + (lane & 3) * 2;
                        *(float2*)(ob + col) =
                            make_float2(acc[mt][nt][2 * half], acc[mt][nt][2 * half + 1]);
                    }
                }
            }
        }
    }
}

// ---------------- combine ----------------------------------------------------
__global__ void combine_kernel(float* __restrict__ out) {
    int idx = blockIdx.x * blockDim.x + threadIdx.x;
    if (idx >= T_ * H_ / 4) return;
    int t = idx >> 9;
    int h = (idx & 511) << 2;
    float w0 = g_topw[2 * t], w1 = g_topw[2 * t + 1];
    int s0 = g_slot_of_j[2 * t], s1 = g_slot_of_j[2 * t + 1];
    float4 r = make_float4(0, 0, 0, 0);
    if (s0 >= 0) {
        float4 v = *(const float4*)(g_ybuf + (size_t)s0 * H_ + h);
        r.x += w0 * v.x; r.y += w0 * v.y; r.z += w0 * v.z; r.w += w0 * v.w;
    }
    if (s1 >= 0) {
        float4 v = *(const float4*)(g_ybuf + (size_t)s1 * H_ + h);
        r.x += w1 * v.x; r.y += w1 * v.y; r.z += w1 * v.z; r.w += w1 * v.w;
    }
    *(float4*)(out + (size_t)t * H_ + h) = r;
}

// ---------------- launch ----------------------------------------------------
extern "C" void kernel_launch(void* const* d_in, const int* in_sizes, int n_in,
                              void* d_out, int out_size) {
    const float* x      = (const float*)d_in[0];
    const float* logits = (const float*)d_in[1];
    const float* w13    = (const float*)d_in[2];
    const float* w2     = (const float*)d_in[3];
    float* out          = (float*)d_out;

    static int smem_set = 0;
    if (!smem_set) {
        cudaFuncSetAttribute(gemm1_mma, cudaFuncAttributeMaxDynamicSharedMemorySize, SMEM_TOTAL);
        cudaFuncSetAttribute(gemm2_mma, cudaFuncAttributeMaxDynamicSharedMemorySize, SMEM_TOTAL);
        smem_set = 1;
    }

    router_kernel<<<1, 512>>>(logits);
    prepass_kernel<<<dim3(E_ * (C_ / 128), 4), 256>>>(x);
    gemm1_mma<<<dim3(I_ / 64, E_ * (C_ / 128)), 384, SMEM_TOTAL>>>(w13);
    gemm2_mma<<<dim3(H_ / 128, E_ * (C_ / 128)), 384, SMEM_TOTAL>>>(w2);
    combine_kernel<<<(T_ * H_ / 4 + 255) / 256, 256>>>(out);
}